// round 1
// baseline (speedup 1.0000x reference)
#include <cuda_runtime.h>
#include <cstdint>
#include <math.h>

// Problem constants
#define NN   8
#define MM   4
#define KK   256
#define CGC  64
#define HW   4096          // 64*64
#define TPB  256

// Output layout: concat(q_out, code, logit) as float32
#define Q_ELEMS    (NN*MM*KK*HW)     // 33,554,432
#define CODE_ELEMS (NN*MM*HW)        // 131,072
#define OFF_CODE   Q_ELEMS
#define OFF_LOGIT  (Q_ELEMS + CODE_ELEMS)

// SMEM layout (floats): Wt[64][260] | xs[64][32] | ls[256][33]
#define WT_STRIDE 260
#define LS_STRIDE 33
#define WT_FLOATS (64*WT_STRIDE)            // 16640
#define XS_FLOATS (64*32)                   // 2048
#define LS_FLOATS (KK*LS_STRIDE)            // 8448
#define SMEM_FLOATS (WT_FLOATS + XS_FLOATS + LS_FLOATS)
#define SMEM_BYTES  (SMEM_FLOATS * 4)       // 108,544 B

__device__ __forceinline__ uint32_t tf_rotl(uint32_t x, int d) {
    return __funnelshift_l(x, x, d);
}

// JAX threefry2x32 with key = (0, 42)  [jax.random.key(42)], counter hi = 0.
// Partitionable mode: 32-bit draw = out0 ^ out1 for counter = flat index.
__device__ __forceinline__ uint32_t threefry_bits(uint32_t cnt) {
    const uint32_t ks1 = 42u;
    const uint32_t ks2 = 0x1BD11BDAu ^ 0u ^ 42u;   // 0x1BD11BF0
    uint32_t x0 = 0u;          // cnt_hi(0) + ks0(0)
    uint32_t x1 = cnt + ks1;
#define TFR(r) { x0 += x1; x1 = tf_rotl(x1, r); x1 ^= x0; }
    TFR(13) TFR(15) TFR(26) TFR(6)
    x0 += ks1; x1 += ks2 + 1u;
    TFR(17) TFR(29) TFR(16) TFR(24)
    x0 += ks2; x1 += 0u + 2u;
    TFR(13) TFR(15) TFR(26) TFR(6)
    x0 += 0u;  x1 += ks1 + 3u;
    TFR(17) TFR(29) TFR(16) TFR(24)
    x0 += ks1; x1 += ks2 + 4u;
    TFR(13) TFR(15) TFR(26) TFR(6)
    x0 += ks2; x1 += 0u + 5u;
#undef TFR
    return x0 ^ x1;
}

__global__ void __launch_bounds__(TPB, 2)
mcq_kernel(const float* __restrict__ x,
           const float* __restrict__ w,
           float* __restrict__ out)
{
    extern __shared__ float smem[];
    float* Wt = smem;                    // [64][260]  Wt[c][k] = w[m][k][c]
    float* xs = Wt + WT_FLOATS;          // [64][32]
    float* ls = xs + XS_FLOATS;          // [256][33]  logits then q values
    __shared__ int code_s[32];

    const int b    = blockIdx.x;
    const int tile = b & 127;            // 128 tiles of 32 positions
    const int nm   = b >> 7;
    const int n    = nm >> 2;
    const int m    = nm & 3;
    const int hw_base = tile * 32;
    const int t    = threadIdx.x;
    const int lane = t & 31;
    const int wid  = t >> 5;

    // ---- load W[m] (256x64) transposed into SMEM ----
    const float* wm = w + (size_t)m * (KK * CGC);
    for (int i = t; i < KK * CGC; i += TPB) {
        int k = i >> 6, c = i & 63;
        Wt[c * WT_STRIDE + k] = wm[i];
    }
    // ---- load x tile (64 channels x 32 positions) ----
    const float* xb = x + ((size_t)(n * 256 + m * 64)) * HW + hw_base;
    for (int i = t; i < 2048; i += TPB) {
        int c = i >> 5, p = i & 31;
        xs[i] = xb[(size_t)c * HW + p];
    }
    __syncthreads();

    // ---- GEMM: 256 k x 32 pos, thread = (4 k) x (8 pos) ----
    const int kq = t & 63;               // k4 = kq*4
    const int pg = t >> 6;               // positions pg*8 .. pg*8+7
    float acc[4][8];
#pragma unroll
    for (int i = 0; i < 4; i++)
#pragma unroll
        for (int j = 0; j < 8; j++) acc[i][j] = 0.f;

    const float* wrow = Wt + kq * 4;
    const float* xrow = xs + pg * 8;
#pragma unroll 8
    for (int c = 0; c < 64; c++) {
        float4 wv = *(const float4*)(wrow + c * WT_STRIDE);
        float4 xa = *(const float4*)(xrow + c * 32);
        float4 xbv = *(const float4*)(xrow + c * 32 + 4);
        float xv[8] = {xa.x, xa.y, xa.z, xa.w, xbv.x, xbv.y, xbv.z, xbv.w};
        float wvv[4] = {wv.x, wv.y, wv.z, wv.w};
#pragma unroll
        for (int i = 0; i < 4; i++)
#pragma unroll
            for (int j = 0; j < 8; j++)
                acc[i][j] = fmaf(wvv[i], xv[j], acc[i][j]);
    }
#pragma unroll
    for (int i = 0; i < 4; i++)
#pragma unroll
        for (int j = 0; j < 8; j++)
            ls[(kq * 4 + i) * LS_STRIDE + pg * 8 + j] = acc[i][j];
    __syncthreads();

    // ---- logit writeout (coalesced: warp handles k rows) ----
    const size_t obase = ((size_t)(n * 1024 + m * 256)) * HW + hw_base;
#pragma unroll 4
    for (int r = 0; r < 32; r++) {
        int k = wid + r * 8;
        out[OFF_LOGIT + obase + (size_t)k * HW + lane] = ls[k * LS_STRIDE + lane];
    }
    __syncthreads();

    // ---- per-position softmax + gumbel argmax (warp per position, 4 each) ----
    const uint32_t pos0 = (uint32_t)((n * 4 + m) * HW + hw_base);
    for (int j = 0; j < 4; j++) {
        int p = wid * 4 + j;
        uint32_t cnt_base = (pos0 + (uint32_t)p) * 256u;

        float lv[8];
        float lmax = -1e30f;
#pragma unroll
        for (int q = 0; q < 8; q++) {
            lv[q] = ls[(lane + 32 * q) * LS_STRIDE + p];
            lmax = fmaxf(lmax, lv[q]);
        }
#pragma unroll
        for (int off = 16; off; off >>= 1)
            lmax = fmaxf(lmax, __shfl_xor_sync(0xffffffffu, lmax, off));

        float best = -1e30f;
        int   bk   = KK;
        float esum = 0.f;
        float ev[8];
#pragma unroll
        for (int q = 0; q < 8; q++) {
            int k = lane + 32 * q;
            uint32_t bits = threefry_bits(cnt_base + (uint32_t)k);
            float u = __uint_as_float((bits >> 9) | 0x3f800000u) - 1.0f;
            u = fmaxf(u, 1.17549435e-38f);           // minval = finfo(f32).tiny
            float g = -logf(-logf(u));
            float v = g + lv[q];
            if (v > best) { best = v; bk = k; }      // first-max within lane (k ascending)
            float e = expf(lv[q] - lmax);
            ev[q] = e;
            esum += e;
        }
#pragma unroll
        for (int off = 16; off; off >>= 1)
            esum += __shfl_xor_sync(0xffffffffu, esum, off);
#pragma unroll
        for (int off = 16; off; off >>= 1) {
            float ov = __shfl_xor_sync(0xffffffffu, best, off);
            int   ok = __shfl_xor_sync(0xffffffffu, bk, off);
            if (ov > best || (ov == best && ok < bk)) { best = ov; bk = ok; }
        }
        if (lane == 0) code_s[p] = bk;

        // quantized = (one_hot + probs) - probs, overwrite ls column p
#pragma unroll
        for (int q = 0; q < 8; q++) {
            int k = lane + 32 * q;
            float prob = ev[q] / esum;
            float oh = (k == bk) ? 1.0f : 0.0f;
            float qv = (oh + prob) - prob;
            ls[k * LS_STRIDE + p] = qv;
        }
    }
    __syncthreads();

    // ---- q_out writeout (coalesced) ----
#pragma unroll 4
    for (int r = 0; r < 32; r++) {
        int k = wid + r * 8;
        out[obase + (size_t)k * HW + lane] = ls[k * LS_STRIDE + lane];
    }
    // ---- code writeout (as float) ----
    if (wid == 0) {
        out[OFF_CODE + (size_t)pos0 + lane] = (float)code_s[lane];
    }
}

extern "C" void kernel_launch(void* const* d_in, const int* in_sizes, int n_in,
                              void* d_out, int out_size)
{
    const float* x = (const float*)d_in[0];
    const float* w = (const float*)d_in[1];
    float* out = (float*)d_out;

    cudaFuncSetAttribute(mcq_kernel,
                         cudaFuncAttributeMaxDynamicSharedMemorySize,
                         SMEM_BYTES);
    dim3 grid(NN * MM * (HW / 32));   // 4096 blocks
    mcq_kernel<<<grid, TPB, SMEM_BYTES>>>(x, w, out);
}